// round 5
// baseline (speedup 1.0000x reference)
#include <cuda_runtime.h>
#include <cuda_bf16.h>
#include <cstdint>

constexpr int B    = 32;
constexpr int H    = 1024;
constexpr int MEL  = 128;
constexpr int TENC = 512;
constexpr int TMEL = 400;
constexpr int H3   = 3 * H;

constexpr size_t OFF_GATE = (size_t)B * TMEL * MEL;
constexpr size_t OFF_MASK = OFF_GATE + (size_t)B * TMEL;

// ---------------- device scratch (no allocations allowed) -------------------
__device__ float WihT0[MEL * H3];          // [k][j]  1.5 MB
__device__ float WhhT0[H * H3];            // 12.6 MB
__device__ float WihT1[H * H3];            // 12.6 MB
__device__ float WhhT1[H * H3];            // 12.6 MB
__device__ float WcT[2 * H * H];           // 8 MB
__device__ float PTw[H * 160];             // [k][c]: c<128 mel, c==128 gate, rest 0

__device__ float g_h0[2][B * H];
__device__ float g_h1[2][B * H];
__device__ float g_decin[B * MEL];
__device__ float g_v[B * H];
__device__ float g_scores[B * TENC];
__device__ float g_ctx[B * H];
__device__ float g_co[B * H];

__device__ float pG[16][B][H3];            // gemm partials (GRU layers) 6.3 MB
__device__ float vp[8][B * H];             // Pv partials
__device__ float cp[16][B * H];            // P5 partials
__device__ float p6p[16][B][160];          // P6 partials

__device__ unsigned g_bar_arrive = 0;
__device__ volatile unsigned g_bar_gen = 0;

// ---------------- helpers ----------------------------------------------------
__device__ __forceinline__ float wsum(float v) {
    v += __shfl_xor_sync(0xffffffffu, v, 16);
    v += __shfl_xor_sync(0xffffffffu, v, 8);
    v += __shfl_xor_sync(0xffffffffu, v, 4);
    v += __shfl_xor_sync(0xffffffffu, v, 2);
    v += __shfl_xor_sync(0xffffffffu, v, 1);
    return v;
}
__device__ __forceinline__ float wmax(float v) {
    v = fmaxf(v, __shfl_xor_sync(0xffffffffu, v, 16));
    v = fmaxf(v, __shfl_xor_sync(0xffffffffu, v, 8));
    v = fmaxf(v, __shfl_xor_sync(0xffffffffu, v, 4));
    v = fmaxf(v, __shfl_xor_sync(0xffffffffu, v, 2));
    v = fmaxf(v, __shfl_xor_sync(0xffffffffu, v, 1));
    return v;
}
__device__ __forceinline__ float sigmoidf_(float x) { return 1.f / (1.f + expf(-x)); }

__device__ __forceinline__ void grid_barrier(int nblk) {
    __syncthreads();
    if (threadIdx.x == 0) {
        __threadfence();
        unsigned gen = g_bar_gen;
        if (atomicAdd(&g_bar_arrive, 1u) == (unsigned)nblk - 1u) {
            g_bar_arrive = 0;
            __threadfence();
            g_bar_gen = gen + 1u;
        } else {
            while (g_bar_gen == gen) {}
        }
        __threadfence();
    }
    __syncthreads();
}

// GEMM micro-kernel: lane owns one output column; 16 batch accumulators.
// Wt points at WT[k0*ld + j0 + lane]; X[bb*xs + k] is broadcast-loaded.
__device__ __forceinline__ void gemm16(const float* __restrict__ Wt, int ld,
                                       const float* __restrict__ X, int xs,
                                       int klen, float acc[16]) {
#pragma unroll 2
    for (int k = 0; k < klen; k += 4) {
        float w0 = Wt[(size_t)(k + 0) * ld];
        float w1 = Wt[(size_t)(k + 1) * ld];
        float w2 = Wt[(size_t)(k + 2) * ld];
        float w3 = Wt[(size_t)(k + 3) * ld];
#pragma unroll
        for (int bb = 0; bb < 16; ++bb) {
            float4 xv = *reinterpret_cast<const float4*>(X + (size_t)bb * xs + k);
            acc[bb] = fmaf(w0, xv.x, fmaf(w1, xv.y, fmaf(w2, xv.z, fmaf(w3, xv.w, acc[bb]))));
        }
    }
}

// Tiled transpose: dst[k*R + j] = src[j*C + k]
__device__ void transpose_mat(const float* __restrict__ src, float* __restrict__ dst,
                              int R, int C, int bx, int nblk, int tid,
                              float (*tile)[33]) {
    int x = tid & 31, y = tid >> 5;            // y in 0..15
    int ntr = R >> 5, ntc = C >> 5;
    for (int t = bx; t < ntr * ntc; t += nblk) {
        int tr = t / ntc, tc = t % ntc;
        __syncthreads();
        tile[y][x]      = src[(size_t)(tr * 32 + y) * C + tc * 32 + x];
        tile[y + 16][x] = src[(size_t)(tr * 32 + y + 16) * C + tc * 32 + x];
        __syncthreads();
        dst[(size_t)(tc * 32 + y) * R + tr * 32 + x]      = tile[x][y];
        dst[(size_t)(tc * 32 + y + 16) * R + tr * 32 + x] = tile[x][y + 16];
    }
}

// ---------------- main persistent kernel -------------------------------------
__global__ void __launch_bounds__(512, 1)
decoder_kernel(const float* __restrict__ enc_hidden,
               const float* __restrict__ enc_out,
               const int*   __restrict__ lens,
               const float* __restrict__ W_attn, const float* __restrict__ b_attn,
               const float* __restrict__ Wih0, const float* __restrict__ Whh0,
               const float* __restrict__ bih0, const float* __restrict__ bhh0,
               const float* __restrict__ Wih1, const float* __restrict__ Whh1,
               const float* __restrict__ bih1, const float* __restrict__ bhh1,
               const float* __restrict__ Wc,   const float* __restrict__ bc,
               const float* __restrict__ Wp,   const float* __restrict__ bp,
               const float* __restrict__ Wg,   const float* __restrict__ bg,
               float* __restrict__ out, int nblk) {
    __shared__ float tile[32][33];
    const int tid  = threadIdx.x;
    const int lane = tid & 31;
    const int wid  = tid >> 5;
    const int bx   = blockIdx.x;
    const int jw   = wid * nblk + bx;            // SMSP-spread job index
    const int GW   = nblk * 16;
    const int gtid = bx * blockDim.x + tid;
    const int gsz  = nblk * blockDim.x;

    // ================= init =================
    transpose_mat(Wih0, WihT0, H3, MEL, bx, nblk, tid, tile);
    transpose_mat(Whh0, WhhT0, H3, H,   bx, nblk, tid, tile);
    transpose_mat(Wih1, WihT1, H3, H,   bx, nblk, tid, tile);
    transpose_mat(Whh1, WhhT1, H3, H,   bx, nblk, tid, tile);
    transpose_mat(Wc,   WcT,   H, 2 * H, bx, nblk, tid, tile);

    for (int idx = gtid; idx < H * 160; idx += gsz) {
        int k = idx / 160, c = idx - k * 160;
        PTw[idx] = (c < MEL) ? Wp[(size_t)c * H + k] : (c == MEL ? Wg[k] : 0.f);
    }
    for (int i = gtid; i < B * H; i += gsz) {
        g_h0[0][i] = enc_hidden[i];
        g_h1[0][i] = enc_hidden[B * H + i];
    }
    for (int i = gtid; i < B * MEL; i += gsz) g_decin[i] = 0.f;
    for (int i = gtid; i < B * TMEL; i += gsz) {
        int b = i / TMEL, t = i - b * TMEL;
        out[OFF_MASK + i] = (t > lens[b]) ? 1.f : 0.f;
    }
    grid_barrier(nblk);

    // ================= 400 autoregressive steps =================
    for (int step = 0; step < TMEL; ++step) {
        const int cur = step & 1, nxt = cur ^ 1;

        // ---- A: GRU0 GEMMs (x-side: 192 jobs, h-side: 1536 jobs) ----
        for (int job = jw; job < 192 + 1536; job += GW) {
            float acc[16];
#pragma unroll
            for (int i = 0; i < 16; ++i) acc[i] = 0.f;
            int jg, b0, slot;
            if (job < 192) {
                jg = job >> 1; b0 = (job & 1) * 16; slot = 0;
                gemm16(WihT0 + jg * 32 + lane, H3, g_decin + b0 * MEL, MEL, MEL, acc);
            } else {
                int q = job - 192;
                jg = q >> 4; b0 = ((q >> 3) & 1) * 16; int kc = q & 7; slot = 1 + kc;
                gemm16(WhhT0 + (size_t)(kc * 128) * H3 + jg * 32 + lane, H3,
                       g_h0[cur] + b0 * H + kc * 128, H, 128, acc);
            }
            const int j = jg * 32 + lane;
#pragma unroll
            for (int bb = 0; bb < 16; ++bb) pG[slot][b0 + bb][j] = acc[bb];
        }
        grid_barrier(nblk);

        // ---- B: combine GRU0 ----
        for (int idx = gtid; idx < B * H; idx += gsz) {
            int b = idx >> 10, c = idx & (H - 1);
            float sx[3], sh[3];
#pragma unroll
            for (int g = 0; g < 3; ++g) {
                int j = g * H + c;
                sx[g] = pG[0][b][j];
                float s = 0.f;
#pragma unroll
                for (int p = 1; p <= 8; ++p) s += pG[p][b][j];
                sh[g] = s;
            }
            float r = sigmoidf_(sx[0] + sh[0] + bih0[c] + bhh0[c]);
            float z = sigmoidf_(sx[1] + sh[1] + bih0[H + c] + bhh0[H + c]);
            float n = tanhf(sx[2] + bih0[2 * H + c] + r * (sh[2] + bhh0[2 * H + c]));
            g_h0[nxt][idx] = (1.f - z) * n + z * g_h0[cur][idx];
        }
        grid_barrier(nblk);

        // ---- C: GRU1 GEMMs (x-side 1536 + h-side 1536) ----
        for (int job = jw; job < 3072; job += GW) {
            float acc[16];
#pragma unroll
            for (int i = 0; i < 16; ++i) acc[i] = 0.f;
            int q = job, slot;
            if (q < 1536) {
                int jg = q >> 4, b0 = ((q >> 3) & 1) * 16, kc = q & 7; slot = kc;
                gemm16(WihT1 + (size_t)(kc * 128) * H3 + jg * 32 + lane, H3,
                       g_h0[nxt] + b0 * H + kc * 128, H, 128, acc);
                const int j = jg * 32 + lane;
#pragma unroll
                for (int bb = 0; bb < 16; ++bb) pG[slot][b0 + bb][j] = acc[bb];
            } else {
                q -= 1536;
                int jg = q >> 4, b0 = ((q >> 3) & 1) * 16, kc = q & 7; slot = 8 + kc;
                gemm16(WhhT1 + (size_t)(kc * 128) * H3 + jg * 32 + lane, H3,
                       g_h1[cur] + b0 * H + kc * 128, H, 128, acc);
                const int j = jg * 32 + lane;
#pragma unroll
                for (int bb = 0; bb < 16; ++bb) pG[slot][b0 + bb][j] = acc[bb];
            }
        }
        grid_barrier(nblk);

        // ---- D: combine GRU1 ----
        for (int idx = gtid; idx < B * H; idx += gsz) {
            int b = idx >> 10, c = idx & (H - 1);
            float sx[3], sh[3];
#pragma unroll
            for (int g = 0; g < 3; ++g) {
                int j = g * H + c;
                float s1 = 0.f, s2 = 0.f;
#pragma unroll
                for (int p = 0; p < 8; ++p) s1 += pG[p][b][j];
#pragma unroll
                for (int p = 8; p < 16; ++p) s2 += pG[p][b][j];
                sx[g] = s1; sh[g] = s2;
            }
            float r = sigmoidf_(sx[0] + sh[0] + bih1[c] + bhh1[c]);
            float z = sigmoidf_(sx[1] + sh[1] + bih1[H + c] + bhh1[H + c]);
            float n = tanhf(sx[2] + bih1[2 * H + c] + r * (sh[2] + bhh1[2 * H + c]));
            g_h1[nxt][idx] = (1.f - z) * n + z * g_h1[cur][idx];
        }
        grid_barrier(nblk);

        const float* h1n = g_h1[nxt];

        // ---- E: Pv  v[b,c] = sum_j h1[b,j] * W_attn[j,c]  (512 jobs) ----
        for (int job = jw; job < 512; job += GW) {
            int cg = job >> 4, b0 = ((job >> 3) & 1) * 16, kc = job & 7;
            float acc[16];
#pragma unroll
            for (int i = 0; i < 16; ++i) acc[i] = 0.f;
            gemm16(W_attn + (size_t)(kc * 128) * H + cg * 32 + lane, H,
                   h1n + b0 * H + kc * 128, H, 128, acc);
            const int c = cg * 32 + lane;
#pragma unroll
            for (int bb = 0; bb < 16; ++bb) vp[kc][(b0 + bb) * H + c] = acc[bb];
        }
        grid_barrier(nblk);

        // ---- Ec: v = sum partials ----
        for (int idx = gtid; idx < B * H; idx += gsz) {
            float s = 0.f;
#pragma unroll
            for (int p = 0; p < 8; ++p) s += vp[p][idx];
            g_v[idx] = s;
        }
        grid_barrier(nblk);

        // ---- P3: scores[b,t] = v[b,:] . enc_out[b,t,:]  (2048 jobs, fp32) ----
        for (int job = jw; job < 2048; job += GW) {
            const int b  = job >> 6;
            const int t0 = (job & 63) * 8;
            float acc[8];
#pragma unroll
            for (int i = 0; i < 8; ++i) acc[i] = 0.f;
            const float4* vb = reinterpret_cast<const float4*>(g_v + (size_t)b * H);
            const float4* Eb = reinterpret_cast<const float4*>(
                enc_out + ((size_t)b * TENC + t0) * H);
            for (int k = lane; k < 256; k += 32) {
                float4 vv = vb[k];
#pragma unroll
                for (int t = 0; t < 8; ++t) {
                    float4 ev = Eb[(size_t)t * 256 + k];
                    acc[t] = fmaf(vv.x, ev.x, fmaf(vv.y, ev.y,
                             fmaf(vv.z, ev.z, fmaf(vv.w, ev.w, acc[t]))));
                }
            }
#pragma unroll
            for (int t = 0; t < 8; ++t) {
                float s = wsum(acc[t]);
                if (lane == t) g_scores[b * TENC + t0 + t] = s;
            }
        }
        grid_barrier(nblk);

        // ---- P4: softmax + context (1024 jobs: b x 32-wide h group, fp32) ----
        for (int job = jw; job < 1024; job += GW) {
            const int b  = job >> 5;
            const int hg = (job & 31) * 32;
            const float* srow = g_scores + b * TENC;
            float sc[16];
            float mx = -1e30f;
#pragma unroll
            for (int i = 0; i < 16; ++i) {
                sc[i] = srow[i * 32 + lane];
                mx = fmaxf(mx, sc[i]);
            }
            mx = wmax(mx);
            float sm = 0.f;
#pragma unroll
            for (int i = 0; i < 16; ++i) { sc[i] = expf(sc[i] - mx); sm += sc[i]; }
            sm = wsum(sm);
            const float inv = 1.f / sm;

            float acc = 0.f;
            const float* ep = enc_out + (size_t)b * TENC * H + hg + lane;
#pragma unroll
            for (int i = 0; i < 16; ++i) {
                float pv = sc[i] * inv;
#pragma unroll 8
                for (int tt = 0; tt < 32; ++tt) {
                    float p  = __shfl_sync(0xffffffffu, pv, tt);
                    float ev = ep[(size_t)(i * 32 + tt) * H];
                    acc = fmaf(p, ev, acc);
                }
            }
            g_ctx[(size_t)b * H + hg + lane] = acc;
        }
        grid_barrier(nblk);

        // ---- P5: co GEMM over [h1; ctx] (1024 jobs) ----
        for (int job = jw; job < 1024; job += GW) {
            int jg = job >> 5, b0 = ((job >> 4) & 1) * 16, kc = job & 15;
            float acc[16];
#pragma unroll
            for (int i = 0; i < 16; ++i) acc[i] = 0.f;
            const float* X = (kc < 8) ? (h1n + b0 * H + kc * 128)
                                      : (g_ctx + b0 * H + (kc - 8) * 128);
            gemm16(WcT + (size_t)(kc * 128) * H + jg * 32 + lane, H, X, H, 128, acc);
            const int j = jg * 32 + lane;
#pragma unroll
            for (int bb = 0; bb < 16; ++bb) cp[kc][(b0 + bb) * H + j] = acc[bb];
        }
        grid_barrier(nblk);

        // ---- P5c: co = tanh(sum + bc) ----
        for (int idx = gtid; idx < B * H; idx += gsz) {
            int c = idx & (H - 1);
            float s = 0.f;
#pragma unroll
            for (int p = 0; p < 16; ++p) s += cp[p][idx];
            g_co[idx] = tanhf(s + bc[c]);
        }
        grid_barrier(nblk);

        // ---- P6: mel/gate GEMM (160 jobs, kc=64) ----
        for (int job = jw; job < 160; job += GW) {
            int cg = job % 5, rest = job / 5;
            int b0 = (rest & 1) * 16, kc = rest >> 1;
            float acc[16];
#pragma unroll
            for (int i = 0; i < 16; ++i) acc[i] = 0.f;
            gemm16(PTw + (size_t)(kc * 64) * 160 + cg * 32 + lane, 160,
                   g_co + b0 * H + kc * 64, H, 64, acc);
            const int c = cg * 32 + lane;
#pragma unroll
            for (int bb = 0; bb < 16; ++bb) p6p[kc][b0 + bb][c] = acc[bb];
        }
        grid_barrier(nblk);

        // ---- P6c: bias + mask + write outputs + next decoder input ----
        for (int idx = gtid; idx < B * 160; idx += gsz) {
            int b = idx / 160, m = idx - b * 160;
            if (m > MEL) continue;
            float s = 0.f;
#pragma unroll
            for (int p = 0; p < 16; ++p) s += p6p[p][b][m];
            const bool msk = step > lens[b];
            if (m < MEL) {
                float val = s + bp[m];
                g_decin[b * MEL + m] = val;
                out[((size_t)b * TMEL + step) * MEL + m] = msk ? 0.f : val;
            } else {
                float gv = s + bg[0];
                out[OFF_GATE + (size_t)b * TMEL + step] = msk ? 1000.f : gv;
            }
        }
        grid_barrier(nblk);
    }
}

// ---------------- host launch -------------------------------------------------
extern "C" void kernel_launch(void* const* d_in, const int* in_sizes, int n_in,
                              void* d_out, int out_size) {
    (void)in_sizes; (void)n_in; (void)out_size;
    int dev = 0;
    cudaGetDevice(&dev);
    int sms = 0;
    cudaDeviceGetAttribute(&sms, cudaDevAttrMultiProcessorCount, dev);
    if (sms <= 0) sms = 148;

    decoder_kernel<<<sms, 512>>>(
        (const float*)d_in[0],   // encoder_hidden [4,B,H]
        (const float*)d_in[1],   // encoder_outputs [B,TENC,H]
        (const int*)d_in[3],     // mel_spec_lens [B]   (d_in[2] = y, unused)
        (const float*)d_in[4],  (const float*)d_in[5],    // W_attn, b_attn
        (const float*)d_in[6],  (const float*)d_in[7],    // W_ih0, W_hh0
        (const float*)d_in[8],  (const float*)d_in[9],    // b_ih0, b_hh0
        (const float*)d_in[10], (const float*)d_in[11],   // W_ih1, W_hh1
        (const float*)d_in[12], (const float*)d_in[13],   // b_ih1, b_hh1
        (const float*)d_in[14], (const float*)d_in[15],   // Wc, bc
        (const float*)d_in[16], (const float*)d_in[17],   // Wp, bp
        (const float*)d_in[18], (const float*)d_in[19],   // Wg, bg
        (float*)d_out, sms);
}